// round 2
// baseline (speedup 1.0000x reference)
#include <cuda_runtime.h>

// ---------------- problem constants ----------------
constexpr int Dn   = 8;
constexpr int Ln   = 12;
constexpr int Cn   = 9;
constexpr int Wn   = 128;
constexpr int Bn   = 4096;
constexpr float EPSf = 1e-5f;

constexpr int OC1   = 32;
constexpr int KK    = 9;
constexpr int W1OUT = 120;   // 128-9+1
constexpr int P1W   = 60;
constexpr int OC2   = 64;
constexpr int W2OUT = 52;    // 60-9+1
constexpr int P2W   = 26;
constexpr int FCIN  = OC2 * P2W;  // 1664

constexpr int NCHUNK  = 19;   // batch chunks per domain -> 8*19 = 152 blocks
constexpr int THREADS = 512;

// ---------------- device scratch (no allocations allowed) ----------------
__device__ float g_partial[2][Cn][32];          // [sum|sumsq][c][j]
__device__ float g_mean[Cn];
__device__ float g_istd[Cn];
__device__ float g_branch[Dn * Bn * Ln];        // per-domain branch outputs

// ---------------- stage 1: per-channel partial sums ----------------
__global__ void stats_partial_kernel(const float* __restrict__ x) {
    const int c   = blockIdx.x;      // 0..8
    const int j   = blockIdx.y;      // 0..31
    const int tid = threadIdx.x;     // 0..127 == w
    float s = 0.f, q = 0.f;
    #pragma unroll 4
    for (int bi = 0; bi < 128; bi++) {
        const int b = j * 128 + bi;
        float v = x[(b * Cn + c) * Wn + tid];
        s += v;
        q = fmaf(v, v, q);
    }
    __shared__ float ss[128], sq[128];
    ss[tid] = s; sq[tid] = q;
    __syncthreads();
    for (int off = 64; off; off >>= 1) {
        if (tid < off) { ss[tid] += ss[tid + off]; sq[tid] += sq[tid + off]; }
        __syncthreads();
    }
    if (tid == 0) { g_partial[0][c][j] = ss[0]; g_partial[1][c][j] = sq[0]; }
}

// ---------------- stage 2: finalize mean / istd ----------------
__global__ void stats_final_kernel() {
    const int c    = threadIdx.x >> 5;
    const int lane = threadIdx.x & 31;
    if (c < Cn) {
        float s = g_partial[0][c][lane];
        float q = g_partial[1][c][lane];
        #pragma unroll
        for (int off = 16; off; off >>= 1) {
            s += __shfl_down_sync(0xffffffffu, s, off);
            q += __shfl_down_sync(0xffffffffu, q, off);
        }
        if (lane == 0) {
            const float invN = 1.0f / (float)(Bn * Wn);
            float mean = s * invN;
            float var  = q * invN - mean * mean;
            g_mean[c] = mean;
            g_istd[c] = rsqrtf(var + EPSf);
        }
    }
}

// ---------------- stage 3: the branch network ----------------
// smem layout (floats)
constexpr int OFF_W1F = 0;                       // 32*81 = 2592
constexpr int OFF_B1F = OFF_W1F + OC1 * 81;      // 32
constexpr int OFF_W2  = OFF_B1F + 32;            // 64*288 = 18432
constexpr int OFF_B2  = OFF_W2 + OC2 * 288;      // 64
constexpr int OFF_FCW = OFF_B2 + 64;             // 12*1664 = 19968
constexpr int OFF_FCB = OFF_FCW + Ln * FCIN;     // 12
constexpr int OFF_A   = OFF_FCB + Ln;            // 12 (padded, only 9 used)
constexpr int OFF_OFF = OFF_A + 12;              // 12 (padded)
constexpr int OFF_X   = OFF_OFF + 12;            // 9*128 = 1152 (16B aligned)
constexpr int OFF_P1  = OFF_X + Cn * Wn;         // 32*60 = 1920
constexpr int OFF_P2  = OFF_P1 + OC1 * P1W;      // 64*26 = 1664
constexpr int SMEM_FLOATS = OFF_P2 + OC2 * P2W;  // 45860
constexpr int SMEM_BYTES  = SMEM_FLOATS * 4;     // 183440

static_assert(OFF_X % 4 == 0, "x buffer must be float4 aligned");

__global__ void __launch_bounds__(THREADS, 1)
branch_kernel(const float* __restrict__ x,
              const float* __restrict__ gamma, const float* __restrict__ beta,
              const float* __restrict__ w1, const float* __restrict__ b1,
              const float* __restrict__ w2, const float* __restrict__ b2,
              const float* __restrict__ fcw, const float* __restrict__ fcb)
{
    extern __shared__ float sm[];
    float* s_w1f = sm + OFF_W1F;
    float* s_b1f = sm + OFF_B1F;
    float* s_w2  = sm + OFF_W2;
    float* s_b2  = sm + OFF_B2;
    float* s_fcw = sm + OFF_FCW;
    float* s_fcb = sm + OFF_FCB;
    float* s_a   = sm + OFF_A;
    float* s_off = sm + OFF_OFF;
    float* s_x   = sm + OFF_X;
    float* s_p1  = sm + OFF_P1;
    float* s_p2  = sm + OFF_P2;

    const int d     = blockIdx.x;
    const int chunk = blockIdx.y;
    const int tid   = threadIdx.x;
    const int wid   = tid >> 5;
    const int lane  = tid & 31;

    // fold BN affine: xn = x*a[c] + off[c]
    if (tid < Cn) {
        float a = g_istd[tid] * gamma[d * Cn + tid];
        s_a[tid]   = a;
        s_off[tid] = beta[d * Cn + tid] - g_mean[tid] * a;
    }
    __syncthreads();

    // w1' = w1 * a[ic];  b1' = b1 + sum w1*off[ic]
    for (int i = tid; i < OC1 * 81; i += THREADS) {
        int ic = (i % 81) / 9;
        s_w1f[i] = w1[d * OC1 * 81 + i] * s_a[ic];
    }
    if (tid < OC1) {
        float s = b1[d * OC1 + tid];
        const float* wr = w1 + (d * OC1 + tid) * 81;
        #pragma unroll
        for (int ic = 0; ic < Cn; ic++) {
            float o = s_off[ic];
            #pragma unroll
            for (int k = 0; k < KK; k++) s = fmaf(wr[ic * 9 + k], o, s);
        }
        s_b1f[tid] = s;
    }
    // copy w2 / b2 / fcw / fcb
    {
        const float4* w2g = (const float4*)(w2 + (size_t)d * OC2 * 288);
        float4* w2s = (float4*)s_w2;
        for (int i = tid; i < OC2 * 288 / 4; i += THREADS) w2s[i] = w2g[i];
        if (tid < OC2) s_b2[tid] = b2[d * OC2 + tid];
        const float4* fcwg = (const float4*)(fcw + (size_t)d * Ln * FCIN);
        float4* fcws = (float4*)s_fcw;
        for (int i = tid; i < Ln * FCIN / 4; i += THREADS) fcws[i] = fcwg[i];
        if (tid < Ln) s_fcb[tid] = fcb[d * Ln + tid];
    }
    __syncthreads();

    for (int b = chunk; b < Bn; b += NCHUNK) {
        // ---- load raw x row into smem ----
        {
            const float4* xg = (const float4*)(x + (size_t)b * Cn * Wn);
            float4* xs = (float4*)s_x;
            for (int i = tid; i < Cn * Wn / 4; i += THREADS) xs[i] = xg[i];
        }
        __syncthreads();

        // ---- conv1 + relu + pool -> p1[32][60] ----
        // warp wid -> oc {2w, 2w+1}; lane<30 -> ow 4l..4l+3 (pools 2l, 2l+1)
        {
            const int oc0 = wid * 2;
            if (lane < 30) {
                float acc[2][4];
                #pragma unroll
                for (int o = 0; o < 2; o++)
                    #pragma unroll
                    for (int jj = 0; jj < 4; jj++) acc[o][jj] = 0.f;
                #pragma unroll 1
                for (int ic = 0; ic < Cn; ic++) {
                    const float4* xr = (const float4*)(s_x + ic * Wn + lane * 4);
                    float4 v0 = xr[0], v1 = xr[1], v2 = xr[2];
                    float xwin[12] = {v0.x, v0.y, v0.z, v0.w,
                                      v1.x, v1.y, v1.z, v1.w,
                                      v2.x, v2.y, v2.z, v2.w};
                    const float* wr0 = s_w1f + (oc0    ) * 81 + ic * 9;
                    const float* wr1 = s_w1f + (oc0 + 1) * 81 + ic * 9;
                    #pragma unroll
                    for (int k = 0; k < KK; k++) {
                        float wa = wr0[k], wb = wr1[k];
                        #pragma unroll
                        for (int jj = 0; jj < 4; jj++) {
                            acc[0][jj] = fmaf(wa, xwin[k + jj], acc[0][jj]);
                            acc[1][jj] = fmaf(wb, xwin[k + jj], acc[1][jj]);
                        }
                    }
                }
                #pragma unroll
                for (int o = 0; o < 2; o++) {
                    float bb = s_b1f[oc0 + o];
                    float r0 = fmaxf(acc[o][0] + bb, 0.f);
                    float r1 = fmaxf(acc[o][1] + bb, 0.f);
                    float r2 = fmaxf(acc[o][2] + bb, 0.f);
                    float r3 = fmaxf(acc[o][3] + bb, 0.f);
                    s_p1[(oc0 + o) * P1W + lane * 2    ] = fmaxf(r0, r1);
                    s_p1[(oc0 + o) * P1W + lane * 2 + 1] = fmaxf(r2, r3);
                }
            }
        }
        __syncthreads();

        // ---- conv2 + relu + pool -> p2[64][26] ----
        // warp wid -> oc {4w..4w+3}; lane<26 -> pool p=lane (ow 2l,2l+1)
        {
            const int oc0 = wid * 4;
            if (lane < P2W) {
                float acc[4][2];
                #pragma unroll
                for (int o = 0; o < 4; o++) { acc[o][0] = 0.f; acc[o][1] = 0.f; }
                #pragma unroll 1
                for (int ic = 0; ic < OC1; ic++) {
                    const float2* xr = (const float2*)(s_p1 + ic * P1W + lane * 2);
                    float xwin[10];
                    #pragma unroll
                    for (int t = 0; t < 5; t++) {
                        float2 v = xr[t];
                        xwin[2 * t] = v.x; xwin[2 * t + 1] = v.y;
                    }
                    #pragma unroll
                    for (int k = 0; k < KK; k++) {
                        #pragma unroll
                        for (int o = 0; o < 4; o++) {
                            float wv = s_w2[(oc0 + o) * 288 + ic * 9 + k];
                            acc[o][0] = fmaf(wv, xwin[k    ], acc[o][0]);
                            acc[o][1] = fmaf(wv, xwin[k + 1], acc[o][1]);
                        }
                    }
                }
                #pragma unroll
                for (int o = 0; o < 4; o++) {
                    float bb = s_b2[oc0 + o];
                    float r0 = fmaxf(acc[o][0] + bb, 0.f);
                    float r1 = fmaxf(acc[o][1] + bb, 0.f);
                    s_p2[(oc0 + o) * P2W + lane] = fmaxf(r0, r1);
                }
            }
        }
        __syncthreads();

        // ---- FC (12 x 1664) + relu -> g_branch ----
        if (wid < Ln) {
            float s = 0.f;
            const float* wr = s_fcw + wid * FCIN;
            #pragma unroll 4
            for (int i = lane; i < FCIN; i += 32)
                s = fmaf(wr[i], s_p2[i], s);
            #pragma unroll
            for (int off = 16; off; off >>= 1)
                s += __shfl_down_sync(0xffffffffu, s, off);
            if (lane == 0) {
                float v = fmaxf(s + s_fcb[wid], 0.f);
                g_branch[((size_t)d * Bn + b) * Ln + wid] = v;
            }
        }
        __syncthreads();
    }
}

// ---------------- stage 4: weighted domain combine ----------------
__global__ void combine_kernel(const float* __restrict__ weights,
                               float* __restrict__ out)
{
    const int idx = blockIdx.x * blockDim.x + threadIdx.x;
    if (idx >= Bn * Ln) return;
    const int b = idx / Ln;
    const int l = idx - b * Ln;
    float s = 0.f;
    #pragma unroll
    for (int d = 0; d < Dn; d++)
        s = fmaf(weights[b * Dn + d], g_branch[((size_t)d * Bn + b) * Ln + l], s);
    out[idx] = s;
}

// ---------------- launch ----------------
extern "C" void kernel_launch(void* const* d_in, const int* in_sizes, int n_in,
                              void* d_out, int out_size)
{
    const float* x       = (const float*)d_in[0];
    const float* weights = (const float*)d_in[1];
    const float* gamma   = (const float*)d_in[2];
    const float* beta    = (const float*)d_in[3];
    const float* w1      = (const float*)d_in[4];
    const float* b1      = (const float*)d_in[5];
    const float* w2      = (const float*)d_in[6];
    const float* b2      = (const float*)d_in[7];
    const float* fcw     = (const float*)d_in[8];
    const float* fcb     = (const float*)d_in[9];
    float* out = (float*)d_out;

    cudaFuncSetAttribute(branch_kernel,
                         cudaFuncAttributeMaxDynamicSharedMemorySize, SMEM_BYTES);

    stats_partial_kernel<<<dim3(Cn, 32), 128>>>(x);
    stats_final_kernel<<<1, Cn * 32>>>();
    branch_kernel<<<dim3(Dn, NCHUNK), THREADS, SMEM_BYTES>>>(
        x, gamma, beta, w1, b1, w2, b2, fcw, fcb);
    combine_kernel<<<(Bn * Ln + 255) / 256, 256>>>(weights, out);
}

// round 3
// speedup vs baseline: 1.4892x; 1.4892x over previous
#include <cuda_runtime.h>

// ---------------- problem constants ----------------
constexpr int Dn   = 8;
constexpr int Ln   = 12;
constexpr int Cn   = 9;
constexpr int Wn   = 128;
constexpr int Bn   = 4096;
constexpr float EPSf = 1e-5f;

constexpr int OC1   = 32;
constexpr int KK    = 9;
constexpr int P1W   = 60;
constexpr int OC2   = 64;
constexpr int P2W   = 26;
constexpr int FCIN  = OC2 * P2W;  // 1664

constexpr int NCHUNK  = 19;   // 8*19 = 152 blocks (1 per SM)
constexpr int THREADS = 512;

typedef unsigned long long ull;

// ---------------- packed f32x2 helpers (SASS FFMA2) ----------------
__device__ __forceinline__ ull ffma2(ull a, ull b, ull c) {
    ull d;
    asm("fma.rn.f32x2 %0, %1, %2, %3;" : "=l"(d) : "l"(a), "l"(b), "l"(c));
    return d;
}
__device__ __forceinline__ ull pack2(float lo, float hi) {
    ull r;
    asm("mov.b64 %0, {%1, %2};" : "=l"(r) : "f"(lo), "f"(hi));
    return r;
}
__device__ __forceinline__ float2 unpack2(ull v) {
    float2 r;
    asm("mov.b64 {%0, %1}, %2;" : "=f"(r.x), "=f"(r.y) : "l"(v));
    return r;
}

// ---------------- device scratch ----------------
__device__ float g_partial[2][Cn][32];
__device__ float g_mean[Cn];
__device__ float g_istd[Cn];
__device__ float g_branch[Dn * Bn * Ln];

// ---------------- stage 1: per-channel partial sums ----------------
__global__ void stats_partial_kernel(const float* __restrict__ x) {
    const int c   = blockIdx.x;
    const int j   = blockIdx.y;
    const int tid = threadIdx.x;     // 0..127 == w
    float s = 0.f, q = 0.f;
    #pragma unroll 4
    for (int bi = 0; bi < 128; bi++) {
        const int b = j * 128 + bi;
        float v = x[(b * Cn + c) * Wn + tid];
        s += v;
        q = fmaf(v, v, q);
    }
    __shared__ float ss[128], sq[128];
    ss[tid] = s; sq[tid] = q;
    __syncthreads();
    for (int off = 64; off; off >>= 1) {
        if (tid < off) { ss[tid] += ss[tid + off]; sq[tid] += sq[tid + off]; }
        __syncthreads();
    }
    if (tid == 0) { g_partial[0][c][j] = ss[0]; g_partial[1][c][j] = sq[0]; }
}

// ---------------- stage 2: finalize mean / istd ----------------
__global__ void stats_final_kernel() {
    const int c    = threadIdx.x >> 5;
    const int lane = threadIdx.x & 31;
    if (c < Cn) {
        float s = g_partial[0][c][lane];
        float q = g_partial[1][c][lane];
        #pragma unroll
        for (int off = 16; off; off >>= 1) {
            s += __shfl_down_sync(0xffffffffu, s, off);
            q += __shfl_down_sync(0xffffffffu, q, off);
        }
        if (lane == 0) {
            const float invN = 1.0f / (float)(Bn * Wn);
            float mean = s * invN;
            float var  = q * invN - mean * mean;
            g_mean[c] = mean;
            g_istd[c] = rsqrtf(var + EPSf);
        }
    }
}

// ---------------- smem layout (floats) ----------------
// weights stored TRANSPOSED: [ic*9+k][oc] so an LDS.64 at oc gives a packed pair
constexpr int OFF_W1T = 0;                       // 81*32  = 2592
constexpr int OFF_B1F = OFF_W1T + 81 * OC1;      // 32
constexpr int OFF_W2T = OFF_B1F + 32;            // 288*64 = 18432
constexpr int OFF_B2  = OFF_W2T + 288 * OC2;     // 64
constexpr int OFF_FCW = OFF_B2 + 64;             // 12*1664 = 19968
constexpr int OFF_FCB = OFF_FCW + Ln * FCIN;     // 12
constexpr int OFF_A   = OFF_FCB + Ln;            // 12 (9 used)
constexpr int OFF_OFF = OFF_A + 12;              // 12
constexpr int OFF_X   = OFF_OFF + 12;            // 9*128 = 1152
constexpr int OFF_P1  = OFF_X + Cn * Wn;         // 32*60 = 1920
constexpr int OFF_P2  = OFF_P1 + OC1 * P1W;      // 64*26 = 1664
constexpr int SMEM_FLOATS = OFF_P2 + OC2 * P2W;
constexpr int SMEM_BYTES  = SMEM_FLOATS * 4;     // 183440

static_assert(OFF_X  % 4 == 0, "x must be float4 aligned");
static_assert(OFF_W1T % 2 == 0 && OFF_W2T % 2 == 0, "8B align for LDS.64");
static_assert(OFF_P1 % 2 == 0 && OFF_P2 % 2 == 0 && OFF_FCW % 2 == 0, "8B align");

__global__ void __launch_bounds__(THREADS, 1)
branch_kernel(const float* __restrict__ x,
              const float* __restrict__ gamma, const float* __restrict__ beta,
              const float* __restrict__ w1, const float* __restrict__ b1,
              const float* __restrict__ w2, const float* __restrict__ b2,
              const float* __restrict__ fcw, const float* __restrict__ fcb)
{
    extern __shared__ float sm[];
    float* s_w1t = sm + OFF_W1T;
    float* s_b1f = sm + OFF_B1F;
    float* s_w2t = sm + OFF_W2T;
    float* s_b2  = sm + OFF_B2;
    float* s_fcw = sm + OFF_FCW;
    float* s_fcb = sm + OFF_FCB;
    float* s_a   = sm + OFF_A;
    float* s_off = sm + OFF_OFF;
    float* s_x   = sm + OFF_X;
    float* s_p1  = sm + OFF_P1;
    float* s_p2  = sm + OFF_P2;

    const int d     = blockIdx.x;
    const int chunk = blockIdx.y;
    const int tid   = threadIdx.x;
    const int wid   = tid >> 5;
    const int lane  = tid & 31;

    // fold BN affine: xn = x*a[c] + off[c]
    if (tid < Cn) {
        float a = g_istd[tid] * gamma[d * Cn + tid];
        s_a[tid]   = a;
        s_off[tid] = beta[d * Cn + tid] - g_mean[tid] * a;
    }
    __syncthreads();

    // w1t[(ic*9+k)*32 + oc] = w1[d][oc][ic][k] * a[ic]
    for (int i = tid; i < 81 * OC1; i += THREADS) {
        int oc  = i & 31;
        int ick = i >> 5;            // ic*9+k
        int ic  = ick / 9;
        s_w1t[i] = w1[(d * OC1 + oc) * 81 + ick] * s_a[ic];
    }
    // b1' = b1 + sum w1*off[ic]
    if (tid < OC1) {
        float s = b1[d * OC1 + tid];
        const float* wr = w1 + (d * OC1 + tid) * 81;
        #pragma unroll
        for (int ic = 0; ic < Cn; ic++) {
            float o = s_off[ic];
            #pragma unroll
            for (int k = 0; k < KK; k++) s = fmaf(wr[ic * 9 + k], o, s);
        }
        s_b1f[tid] = s;
    }
    // w2t[(ic*9+k)*64 + oc] = w2[d][oc][ic*9+k]
    for (int i = tid; i < 288 * OC2; i += THREADS) {
        int oc  = i & 63;
        int ick = i >> 6;
        s_w2t[i] = w2[((size_t)d * OC2 + oc) * 288 + ick];
    }
    if (tid < OC2) s_b2[tid] = b2[d * OC2 + tid];
    {
        const float4* fcwg = (const float4*)(fcw + (size_t)d * Ln * FCIN);
        float4* fcws = (float4*)s_fcw;
        for (int i = tid; i < Ln * FCIN / 4; i += THREADS) fcws[i] = fcwg[i];
        if (tid < Ln) s_fcb[tid] = fcb[d * Ln + tid];
    }
    __syncthreads();

    for (int b = chunk; b < Bn; b += NCHUNK) {
        // ---- load raw x row ----
        {
            const float4* xg = (const float4*)(x + (size_t)b * Cn * Wn);
            float4* xs = (float4*)s_x;
            for (int i = tid; i < Cn * Wn / 4; i += THREADS) xs[i] = xg[i];
        }
        __syncthreads();

        // ---- conv1 + relu + pool -> p1[32][60] ----
        // warp -> oc pair (2w, 2w+1); lane<30 -> ow 4l..4l+3
        {
            const int oc0 = wid * 2;
            if (lane < 30) {
                const ull binit = pack2(s_b1f[oc0], s_b1f[oc0 + 1]);
                ull acc[4] = {binit, binit, binit, binit};
                #pragma unroll 1
                for (int ic = 0; ic < Cn; ic++) {
                    const float4* xr = (const float4*)(s_x + ic * Wn + lane * 4);
                    float4 v0 = xr[0], v1 = xr[1], v2 = xr[2];
                    const float xwin[12] = {v0.x, v0.y, v0.z, v0.w,
                                            v1.x, v1.y, v1.z, v1.w,
                                            v2.x, v2.y, v2.z, v2.w};
                    ull xd[12];
                    #pragma unroll
                    for (int j = 0; j < 12; j++) xd[j] = pack2(xwin[j], xwin[j]);
                    const float* wbase = s_w1t + (ic * 9) * OC1 + oc0;
                    #pragma unroll
                    for (int k = 0; k < KK; k++) {
                        ull wp = *(const ull*)(wbase + k * OC1);
                        #pragma unroll
                        for (int jj = 0; jj < 4; jj++)
                            acc[jj] = ffma2(wp, xd[k + jj], acc[jj]);
                    }
                }
                float2 a0 = unpack2(acc[0]), a1 = unpack2(acc[1]);
                float2 a2 = unpack2(acc[2]), a3 = unpack2(acc[3]);
                s_p1[(oc0    ) * P1W + lane * 2    ] = fmaxf(fmaxf(a0.x, a1.x), 0.f);
                s_p1[(oc0    ) * P1W + lane * 2 + 1] = fmaxf(fmaxf(a2.x, a3.x), 0.f);
                s_p1[(oc0 + 1) * P1W + lane * 2    ] = fmaxf(fmaxf(a0.y, a1.y), 0.f);
                s_p1[(oc0 + 1) * P1W + lane * 2 + 1] = fmaxf(fmaxf(a2.y, a3.y), 0.f);
            }
        }
        __syncthreads();

        // ---- conv2 + relu + pool -> p2[64][26] ----
        // warp -> oc 4w..4w+3 (2 packed pairs); lane<26 -> pool p=lane
        {
            const int oc0 = wid * 4;
            if (lane < P2W) {
                const ull bA = pack2(s_b2[oc0    ], s_b2[oc0 + 1]);
                const ull bB = pack2(s_b2[oc0 + 2], s_b2[oc0 + 3]);
                ull accA0 = bA, accA1 = bA, accB0 = bB, accB1 = bB;
                #pragma unroll 1
                for (int ic = 0; ic < OC1; ic++) {
                    const float2* xr = (const float2*)(s_p1 + ic * P1W + lane * 2);
                    ull xd[10];
                    #pragma unroll
                    for (int t = 0; t < 5; t++) {
                        float2 v = xr[t];
                        xd[2 * t    ] = pack2(v.x, v.x);
                        xd[2 * t + 1] = pack2(v.y, v.y);
                    }
                    const float* wbase = s_w2t + (ic * 9) * OC2 + oc0;
                    #pragma unroll
                    for (int k = 0; k < KK; k++) {
                        ull wpA = *(const ull*)(wbase + k * OC2);
                        ull wpB = *(const ull*)(wbase + k * OC2 + 2);
                        accA0 = ffma2(wpA, xd[k    ], accA0);
                        accA1 = ffma2(wpA, xd[k + 1], accA1);
                        accB0 = ffma2(wpB, xd[k    ], accB0);
                        accB1 = ffma2(wpB, xd[k + 1], accB1);
                    }
                }
                float2 uA0 = unpack2(accA0), uA1 = unpack2(accA1);
                float2 uB0 = unpack2(accB0), uB1 = unpack2(accB1);
                s_p2[(oc0    ) * P2W + lane] = fmaxf(fmaxf(uA0.x, uA1.x), 0.f);
                s_p2[(oc0 + 1) * P2W + lane] = fmaxf(fmaxf(uA0.y, uA1.y), 0.f);
                s_p2[(oc0 + 2) * P2W + lane] = fmaxf(fmaxf(uB0.x, uB1.x), 0.f);
                s_p2[(oc0 + 3) * P2W + lane] = fmaxf(fmaxf(uB0.y, uB1.y), 0.f);
            }
        }
        __syncthreads();

        // ---- FC (12 x 1664) + relu, packed ----
        if (wid < Ln) {
            ull s2 = pack2(0.f, 0.f);
            const float* wr = s_fcw + wid * FCIN;
            #pragma unroll 2
            for (int i = lane; i < FCIN / 2; i += 32) {
                ull wp = *(const ull*)(wr + i * 2);
                ull xp = *(const ull*)(s_p2 + i * 2);
                s2 = ffma2(wp, xp, s2);
            }
            float2 sv = unpack2(s2);
            float s = sv.x + sv.y;
            #pragma unroll
            for (int off = 16; off; off >>= 1)
                s += __shfl_down_sync(0xffffffffu, s, off);
            if (lane == 0)
                g_branch[((size_t)d * Bn + b) * Ln + wid] =
                    fmaxf(s + s_fcb[wid], 0.f);
        }
        __syncthreads();
    }
}

// ---------------- stage 4: weighted domain combine ----------------
__global__ void combine_kernel(const float* __restrict__ weights,
                               float* __restrict__ out)
{
    const int idx = blockIdx.x * blockDim.x + threadIdx.x;
    if (idx >= Bn * Ln) return;
    const int b = idx / Ln;
    const int l = idx - b * Ln;
    float s = 0.f;
    #pragma unroll
    for (int d = 0; d < Dn; d++)
        s = fmaf(weights[b * Dn + d], g_branch[((size_t)d * Bn + b) * Ln + l], s);
    out[idx] = s;
}

// ---------------- launch ----------------
extern "C" void kernel_launch(void* const* d_in, const int* in_sizes, int n_in,
                              void* d_out, int out_size)
{
    const float* x       = (const float*)d_in[0];
    const float* weights = (const float*)d_in[1];
    const float* gamma   = (const float*)d_in[2];
    const float* beta    = (const float*)d_in[3];
    const float* w1      = (const float*)d_in[4];
    const float* b1      = (const float*)d_in[5];
    const float* w2      = (const float*)d_in[6];
    const float* b2      = (const float*)d_in[7];
    const float* fcw     = (const float*)d_in[8];
    const float* fcb     = (const float*)d_in[9];
    float* out = (float*)d_out;

    cudaFuncSetAttribute(branch_kernel,
                         cudaFuncAttributeMaxDynamicSharedMemorySize, SMEM_BYTES);

    stats_partial_kernel<<<dim3(Cn, 32), 128>>>(x);
    stats_final_kernel<<<1, Cn * 32>>>();
    branch_kernel<<<dim3(Dn, NCHUNK), THREADS, SMEM_BYTES>>>(
        x, gamma, beta, w1, b1, w2, b2, fcw, fcb);
    combine_kernel<<<(Bn * Ln + 255) / 256, 256>>>(weights, out);
}